// round 5
// baseline (speedup 1.0000x reference)
#include <cuda_runtime.h>
#include <math.h>

// Shapes
//   amplitudes, frequencies : [8, 250, 100] f32
//   out = concat( amp_env [8, 64000, 100], freq_env [8, 250, 100] )  f32
#define B            8
#define FRAMES       250
#define CH           100
#define CTRL_ELEMS   (B * FRAMES * CH)        // 200000
#define T_OUT        64000
#define HOP          256                      // 64000 / 250
#define ENV_ELEMS    (B * T_OUT * CH)         // 51200000
#define SEGS         (B * FRAMES)             // 2000 segments
#define SEG_VEC4     (HOP * (CH / 4))         // 6400 float4 per segment
#define UP_THREADS   800                      // 32 rows x 25 float4-groups
#define GRID         296                      // 2 blocks / SM, persistent

// ---------------------------------------------------------------------------
// get_controls math for one (segment, channel) pair.
//   amp  = (2*sigmoid(a)^ln(10) + 1e-7) * ((freq*harm < SR/2) + 1e-4)
//   freq = 440 * 2^((sigmoid(f)*MIDI_MAX - 69)/12)
// ---------------------------------------------------------------------------
__device__ __forceinline__ void controls_math(float a, float f, int c,
                                              float& amp_out, float& freq_out) {
    const float LOG10_F  = 2.302585092994046f;   // ln(10)
    const float MIDI_MAX = 119.21309485364912f;  // 12*(log2 8000-log2 440)+69
    const float NYQ      = 22050.0f;             // SR / 2

    float uf   = 1.0f / (1.0f + expf(-f));
    float freq = 440.0f * exp2f((uf * MIDI_MAX - 69.0f) * (1.0f / 12.0f));

    float sa  = 1.0f / (1.0f + expf(-a));
    float amp = 2.0f * powf(sa, LOG10_F) + 1e-7f;

    float aa = ((freq * (float)(c + 1) < NYQ) ? 1.0f : 0.0f) + 1e-4f;

    amp_out  = amp * aa;
    freq_out = freq;
}

// ---------------------------------------------------------------------------
// Persistent fused kernel: 296 blocks, 2 resident per SM (launch_bounds caps
// registers so both fit). Each block loops over segments s = bid, bid+296,...
// Double-buffered smem controls pipeline:
//   iter i: [issue LDGs for seg i+1] -> [8 coalesced streaming stores for
//   seg i] -> [finish controls math for i+1 into other buffer] -> barrier.
// Thread tid owns fixed channel float4-group c4 = tid%25, base row r0=tid/25;
// out[row] = x0 + (x1-x0)*w[row], w[r] = 0.5 - 0.5*cospi(r/256).
// Two co-resident blocks hide each other's barrier/controls bubbles.
// ---------------------------------------------------------------------------
__global__ __launch_bounds__(UP_THREADS, 2) void synth_kernel(
        const float* __restrict__ amp_in,
        const float* __restrict__ freq_in,
        float4* __restrict__ out,
        float* __restrict__ freq_out) {
    // s_amp[buf][which][c]: which=0 -> x0 (this segment), which=1 -> x1 (next)
    __shared__ __align__(16) float s_amp[2][2][CH];
    __shared__ float sw[HOP];

    const int tid = threadIdx.x;
    const int c4  = tid % 25;                 // channel float4-group (fixed)
    const int r0  = tid / 25;                 // base row within segment

    const bool ctl   = (tid < 200);
    const int  which = ctl ? (tid / CH) : 0;  // 0 -> seg, 1 -> segn
    const int  c     = ctl ? (tid - which * CH) : 0;

    // Window table (built by threads not doing controls).
    if (tid >= 544) {
        const int r = tid - 544;              // 0..255
        sw[r] = 0.5f - 0.5f * cospif((float)r * (1.0f / 256.0f));
    }

    int s   = blockIdx.x;
    int buf = 0;

    // Prologue: controls for the first segment into buf 0.
    if (ctl) {
        int ss = s + which;
        if (ss % FRAMES == 0 && which) ss = s;    // clamp at batch boundary
        const int idx = ss * CH + c;
        float amp, frq;
        controls_math(amp_in[idx], freq_in[idx], c, amp, frq);
        s_amp[0][which][c] = amp;
        if (!which) freq_out[idx] = frq;
    }
    __syncthreads();

    while (s < SEGS) {
        const int snext = s + GRID;

        // (a) Issue global loads for the NEXT segment as early as possible.
        float a_nxt = 0.0f, f_nxt = 0.0f;
        int idx_nxt = 0;
        const bool act = ctl && (snext < SEGS);
        if (act) {
            int ss = snext + which;
            if (ss % FRAMES == 0 && which) ss = snext;
            idx_nxt = ss * CH + c;
            a_nxt = amp_in[idx_nxt];
            f_nxt = freq_in[idx_nxt];
        }

        // (b) Stream the current segment's 8 coalesced float4 stores.
        const float4 x0 = *reinterpret_cast<const float4*>(&s_amp[buf][0][c4 * 4]);
        const float4 x1 = *reinterpret_cast<const float4*>(&s_amp[buf][1][c4 * 4]);
        float4 d;
        d.x = x1.x - x0.x;
        d.y = x1.y - x0.y;
        d.z = x1.z - x0.z;
        d.w = x1.w - x0.w;

        float4* o = out + (size_t)s * SEG_VEC4 + tid;
#pragma unroll
        for (int k = 0; k < 8; k++) {
            const float w = sw[r0 + 32 * k];
            float4 v;
            v.x = fmaf(d.x, w, x0.x);
            v.y = fmaf(d.y, w, x0.y);
            v.z = fmaf(d.z, w, x0.z);
            v.w = fmaf(d.w, w, x0.w);
            __stcs(&o[UP_THREADS * k], v);    // streaming: write-once data
        }

        // (c) Finish next segment's controls into the other buffer.
        if (act) {
            float amp, frq;
            controls_math(a_nxt, f_nxt, c, amp, frq);
            s_amp[buf ^ 1][which][c] = amp;
            if (!which) freq_out[idx_nxt] = frq;
        }

        // (d) One barrier per segment.
        __syncthreads();
        buf ^= 1;
        s = snext;
    }
}

// ---------------------------------------------------------------------------
extern "C" void kernel_launch(void* const* d_in, const int* in_sizes, int n_in,
                              void* d_out, int out_size) {
    const float* amps  = (const float*)d_in[0];
    const float* freqs = (const float*)d_in[1];
    float* out = (float*)d_out;

    synth_kernel<<<GRID, UP_THREADS>>>(amps, freqs, (float4*)out,
                                       out + ENV_ELEMS);
}